// round 16
// baseline (speedup 1.0000x reference)
#include <cuda_runtime.h>
#include <cuda_fp16.h>
#include <cstdint>
#include <math.h>

// Shapes: text[256,512] f32, clip[256,512] f32, concept[256,32,512] f32,
// frame[256,64,512] f32, logit_scale scalar, out[256,256] f32.
// Big GEMM S[8192,16384] = nc @ nf^T in f16 (f16 acc), fused
// max-over-64-frames / mean-over-32-tokens epilogue; fp32 g_sim precomputed.
// compute_103 target: mma.sync + cp.async.bulk + mbarrier (no tcgen05).
// R16: CTA tile 256x256 (512 thr, 16 warps = 4M x 4N, warp 64x64),
// THREE-stage 64 KB bulk-copy ring (prefetch 2 ahead) — deeper pipeline
// to absorb delivery jitter that the 2-stage ring exposed.

#define D_K     512
#define A_ROWS  8192
#define B_ROWS  16384
#define NCH     8             // 512 / 64 k-chunks (64 f16 = 128 B per row)
#define MT      64            // A images (128 rows) per chunk
#define NT      128           // B images (128 rows) per chunk
#define AIMG    16384         // 128 rows * 128 B
#define BIMG    16384
#define A_TILE  32768         // 256 rows * 128 B
#define B_TILE  32768
#define STAGE   65536         // A_TILE + B_TILE
#define NSTG    3
#define SMEM_DYN (NSTG * STAGE + 128)   // 192 KB + barrier slab
#define GSIM_BLOCKS 512       // 32 token-groups x 16 video-groups
#define NORM_BLOCKS 1536      // 24576 rows / 16 (half-warp per row)

// Packed, pre-swizzled f16 operand images:
//   g_ncp: [chunk(8)][mtile(64)][16384 B], g_nfp: [chunk(8)][ntile(128)][16384 B]
__device__ __align__(256) unsigned char g_ncp[(size_t)NCH * MT * AIMG];
__device__ __align__(256) unsigned char g_nfp[(size_t)NCH * NT * BIMG];
__device__ __align__(256) float g_gsim[256 * 256];

// ---------------------------------------------------------------------------
__device__ __forceinline__ uint32_t smem_u32(const void* p) {
    uint32_t a;
    asm("{ .reg .u64 t; cvta.to.shared.u64 t, %1; cvt.u32.u64 %0, t; }"
        : "=r"(a) : "l"(p));
    return a;
}
__device__ __forceinline__ void mbar_init(uint32_t a, uint32_t cnt) {
    asm volatile("mbarrier.init.shared.b64 [%0], %1;" :: "r"(a), "r"(cnt) : "memory");
}
__device__ __forceinline__ void mbar_expect_tx(uint32_t a, uint32_t bytes) {
    asm volatile("mbarrier.arrive.expect_tx.shared.b64 _, [%0], %1;"
                 :: "r"(a), "r"(bytes) : "memory");
}
__device__ __forceinline__ void mbar_arrive(uint32_t a) {
    asm volatile("mbarrier.arrive.release.cta.shared::cta.b64 _, [%0];"
                 :: "r"(a) : "memory");
}
#define MBAR_WAIT(mbar, parity) do {                                            \
    asm volatile("{\n\t.reg .pred P;\n"                                         \
        "LW_%=:\n\t"                                                            \
        "mbarrier.try_wait.parity.acquire.cta.shared::cta.b64 P, [%0], %1, 0x989680;\n\t" \
        "@P bra LD_%=;\n\t"                                                     \
        "bra LW_%=;\n"                                                          \
        "LD_%=:\n\t}"                                                           \
        :: "r"(mbar), "r"(parity) : "memory");                                  \
} while (0)
__device__ __forceinline__ void bulk_g2s(uint32_t dst, const void* src,
                                         uint32_t bytes, uint32_t mbar) {
    asm volatile(
        "cp.async.bulk.shared::cluster.global.mbarrier::complete_tx::bytes "
        "[%0], [%1], %2, [%3];"
        :: "r"(dst), "l"(src), "r"(bytes), "r"(mbar) : "memory");
}
__device__ __forceinline__ void fence_proxy_async_cta() {
    asm volatile("fence.proxy.async.shared::cta;" ::: "memory");
}
__device__ __forceinline__ void ldm_x4(uint32_t* r, uint32_t addr) {
    asm volatile("ldmatrix.sync.aligned.m8n8.x4.shared.b16 {%0,%1,%2,%3}, [%4];"
                 : "=r"(r[0]), "=r"(r[1]), "=r"(r[2]), "=r"(r[3]) : "r"(addr));
}
__device__ __forceinline__ void mma16816h(uint32_t* c, const uint32_t* a,
                                          uint32_t b0, uint32_t b1) {
    asm volatile(
        "mma.sync.aligned.m16n8k16.row.col.f16.f16.f16.f16 "
        "{%0,%1}, {%2,%3,%4,%5}, {%6,%7}, {%0,%1};"
        : "+r"(c[0]), "+r"(c[1])
        : "r"(a[0]), "r"(a[1]), "r"(a[2]), "r"(a[3]), "r"(b0), "r"(b1));
}

// ---------------------------------------------------------------------------
// Kernel 1 (single prep launch, 32 KB STATIC shared) — identical to R14:
//   blocks [0, 512): fp32 g_sim tile, 8 tokens x 16 videos, smem clip tile.
//   blocks [512, 2048): L2-normalize -> f16 swizzled images (half-warp/row).
// ---------------------------------------------------------------------------
__global__ __launch_bounds__(256) void prep_kernel(
    const float* __restrict__ text, const float* __restrict__ clip,
    const float* __restrict__ concept_e, const float* __restrict__ frame_e) {
    __shared__ float4 csh[16 * 128];            // 16 videos x 512 f32 = 32 KB
    int wid = threadIdx.x >> 5;
    int lane = threadIdx.x & 31;

    if (blockIdx.x < GSIM_BLOCKS) {
        int b = blockIdx.x;
        int tb = (b >> 4) * 8, vb = (b & 15) * 16;

        const float4* c4 = (const float4*)(clip + (size_t)vb * D_K);
#pragma unroll
        for (int i = 0; i < 8; i++)
            csh[threadIdx.x + i * 256] = c4[threadIdx.x + i * 256];
        __syncthreads();

        int t = tb + wid;
        float4 tv[4];
        const float4* tr = (const float4*)(text + (size_t)t * D_K);
#pragma unroll
        for (int j = 0; j < 4; j++) tv[j] = tr[lane * 4 + j];

        float acc[16];
#pragma unroll 1
        for (int v = 0; v < 16; v++) {
            const float4* cr = csh + v * 128;
            float g = 0.f;
#pragma unroll
            for (int j = 0; j < 4; j++) {
                float4 cv = cr[lane * 4 + j];
                g += tv[j].x * cv.x + tv[j].y * cv.y + tv[j].z * cv.z + tv[j].w * cv.w;
            }
            acc[v] = g;
        }
#pragma unroll
        for (int v = 0; v < 16; v++)
            acc[v] += __shfl_xor_sync(0xffffffffu, acc[v], 16);
#pragma unroll
        for (int off = 8; off > 0; off >>= 1) {
#pragma unroll
            for (int v = 0; v < off; v++) {
                float lo = acc[v], hi = acc[v + off];
                float sent = (lane & off) ? lo : hi;
                float recv = __shfl_xor_sync(0xffffffffu, sent, off);
                acc[v] = ((lane & off) ? hi : lo) + recv;
            }
        }
        if (lane < 16) g_gsim[(size_t)t * 256 + vb + lane] = acc[0];
        return;
    }

    // ---- normalize + f16 + swizzled pack, half-warp per row ----
    int half = lane >> 4, hl = lane & 15;
    int R = (blockIdx.x - GSIM_BLOCKS) * 16 + wid * 2 + half;   // 0..24575

    const float* src;
    unsigned char* img;
    size_t chunk_stride;
    int rowin;
    if (R < A_ROWS) {
        src = concept_e + (size_t)R * D_K;
        img = g_ncp + (size_t)(R >> 7) * AIMG;
        rowin = R & 127;
        chunk_stride = (size_t)MT * AIMG;
    } else {
        int Rf = R - A_ROWS;
        src = frame_e + (size_t)Rf * D_K;
        img = g_nfp + (size_t)(Rf >> 7) * BIMG;
        rowin = Rf & 127;
        chunk_stride = (size_t)NT * BIMG;
    }

    int grp = hl >> 3, seg = hl & 7;
    float4 v[8];
    const float4* s4 = (const float4*)src;
#pragma unroll
    for (int p = 0; p < 4; p++) {
        int chunk = p * 2 + grp;
        int base4 = chunk * 16 + seg * 2;
        v[2 * p]     = s4[base4];
        v[2 * p + 1] = s4[base4 + 1];
    }

    float ss = 0.f;
#pragma unroll
    for (int i = 0; i < 8; i++)
        ss += v[i].x * v[i].x + v[i].y * v[i].y + v[i].z * v[i].z + v[i].w * v[i].w;
#pragma unroll
    for (int off = 8; off > 0; off >>= 1)
        ss += __shfl_xor_sync(0xffffffffu, ss, off);

    float inv = 1.0f / fmaxf(sqrtf(ss), 1e-12f);

    int soff = rowin * 128 + seg * 16;
    int swz = soff ^ ((soff >> 3) & 0x70);
#pragma unroll
    for (int p = 0; p < 4; p++) {
        union { __half2 h[4]; uint4 q; } u;
        u.h[0] = __float22half2_rn(make_float2(v[2*p].x * inv, v[2*p].y * inv));
        u.h[1] = __float22half2_rn(make_float2(v[2*p].z * inv, v[2*p].w * inv));
        u.h[2] = __float22half2_rn(make_float2(v[2*p+1].x * inv, v[2*p+1].y * inv));
        u.h[3] = __float22half2_rn(make_float2(v[2*p+1].z * inv, v[2*p+1].w * inv));
        int chunk = p * 2 + grp;
        *(uint4*)(img + (size_t)chunk * chunk_stride + swz) = u.q;
    }
}

// ---------------------------------------------------------------------------
// Kernel 2: f16 HMMA GEMM, CTA tile 256x256 (K=512), 512 thr, 16 warps
// (4M x 4N, warp 64x64), 3-stage 64 KB bulk-copy ring (prefetch 2 ahead).
// full mbarrier (tx, 1 arrive) + empty mbarrier (16 warp-arrives) per stage.
// ---------------------------------------------------------------------------
__global__ void __launch_bounds__(512, 1) gemm_kernel(
    const float* __restrict__ lsc, float* __restrict__ out) {
    extern __shared__ unsigned char smem[];
    uint32_t sbase = smem_u32(smem);
    uint32_t mb = sbase + NSTG * STAGE;
    // full[0..2] at mb, mb+8, mb+16; empty[0..2] at mb+24, mb+32, mb+40
    uint32_t fullb = mb, empb = mb + 24;

    int tid = threadIdx.x, wid = tid >> 5, lane = tid & 31;
    int mpair = blockIdx.y, npair = blockIdx.x;
    int wm = wid >> 2, wn = wid & 3;             // 4M x 4N

    const unsigned char* asrc = g_ncp + (size_t)mpair * A_TILE;
    const unsigned char* bsrc = g_nfp + (size_t)npair * B_TILE;
    const size_t ACS = (size_t)MT * AIMG;        // 1 MB per chunk
    const size_t BCS = (size_t)NT * BIMG;        // 2 MB per chunk

    // A rows 0..255 span the two 16 KB A images contiguously (row*128)
    uint32_t Aoff[4], Axm[4];
#pragma unroll
    for (int mt = 0; mt < 4; mt++) {
        int row = wm * 64 + mt * 16 + (lane & 15);
        Aoff[mt] = row * 128;
        Axm[mt] = (row & 7) << 4;
    }
    uint32_t kA = (lane & 16);

    uint32_t Boff[4], Bxm[4];
#pragma unroll
    for (int bp = 0; bp < 4; bp++) {
        int row = wn * 64 + bp * 16 + (lane & 7) + ((lane & 16) ? 8 : 0);
        Boff[bp] = A_TILE + row * 128;           // B region after A
        Bxm[bp] = (row & 7) << 4;
    }
    uint32_t kB = (lane & 8) ? 16u : 0u;

    // epilogue scalars preloaded
    int t0 = mpair * 8 + wm * 2;
    int vout = npair * 4 + wn;
    float scale = fminf(expf(lsc[0]), 100.0f);
    float g0 = __ldg(&g_gsim[(size_t)t0 * 256 + vout]);
    float g1 = __ldg(&g_gsim[(size_t)(t0 + 1) * 256 + vout]);

    uint32_t acc[4][8][2];
#pragma unroll
    for (int i = 0; i < 4; i++)
#pragma unroll
        for (int j = 0; j < 8; j++) { acc[i][j][0] = 0u; acc[i][j][1] = 0u; }

    if (tid == 0) {
#pragma unroll
        for (int s = 0; s < NSTG; s++) {
            mbar_init(fullb + s * 8, 1);
            mbar_init(empb + s * 8, 16);         // one arrive per warp
        }
        fence_proxy_async_cta();
    }
    __syncthreads();
    // prologue: prefetch chunks 0 and 1
    if (tid == 0) {
#pragma unroll
        for (int cn = 0; cn < 2; cn++) {
            uint32_t dst = sbase + cn * STAGE;
            uint32_t fb = fullb + cn * 8;
            mbar_expect_tx(fb, STAGE);
            bulk_g2s(dst,          asrc + cn * ACS, A_TILE, fb);
            bulk_g2s(dst + A_TILE, bsrc + cn * BCS, B_TILE, fb);
        }
    }

#pragma unroll 1
    for (int c = 0; c < NCH; c++) {
        // rotating producer: warp ((c+2) & 15) prefetches chunk c+2
        int cn = c + 2;
        if (cn < NCH && wid == (cn & 15) && lane == 0) {
            int s = cn % NSTG;
            uint32_t dst = sbase + s * STAGE;
            uint32_t fb = fullb + s * 8;
            uint32_t eb = empb + s * 8;
            if (cn >= NSTG) MBAR_WAIT(eb, (cn / NSTG - 1) & 1);
            mbar_expect_tx(fb, STAGE);
            bulk_g2s(dst,          asrc + cn * ACS, A_TILE, fb);
            bulk_g2s(dst + A_TILE, bsrc + cn * BCS, B_TILE, fb);
        }

        int st = c % NSTG;
        MBAR_WAIT(fullb + st * 8, (c / NSTG) & 1);

        uint32_t sa = sbase + st * STAGE;

#pragma unroll
        for (int ks = 0; ks < 4; ks++) {
            uint32_t kb = ks * 32;
            uint32_t a[4][4];
#pragma unroll
            for (int mt = 0; mt < 4; mt++)
                ldm_x4(a[mt], sa + Aoff[mt] + ((kb + kA) ^ Axm[mt]));
#pragma unroll
            for (int bp = 0; bp < 4; bp++) {
                uint32_t b[4];
                ldm_x4(b, sa + Boff[bp] + ((kb + kB) ^ Bxm[bp]));
#pragma unroll
                for (int mt = 0; mt < 4; mt++) {
                    mma16816h(acc[mt][2 * bp],     a[mt], b[0], b[1]);
                    mma16816h(acc[mt][2 * bp + 1], a[mt], b[2], b[3]);
                }
            }
        }
        // this warp is done reading stage st; release-arrive on empty
        if (lane == 0) mbar_arrive(empb + st * 8);
    }

    // ---- fused epilogue (register-only; verified R7 mapping) ----
    float rm[4][2];
#pragma unroll
    for (int mt = 0; mt < 4; mt++)
#pragma unroll
        for (int h = 0; h < 2; h++) {
            __half2 m = __halves2half2(__ushort_as_half(0xFBFFu),
                                       __ushort_as_half(0xFBFFu));  // -65504
#pragma unroll
            for (int np = 0; np < 8; np++)
                m = __hmax2(m, *(__half2*)&acc[mt][np][h]);
            float2 f = __half22float2(m);
            rm[mt][h] = fmaxf(f.x, f.y);
        }
#pragma unroll
    for (int off = 1; off <= 2; off <<= 1) {
#pragma unroll
        for (int mt = 0; mt < 4; mt++)
#pragma unroll
            for (int h = 0; h < 2; h++)
                rm[mt][h] = fmaxf(rm[mt][h],
                                  __shfl_xor_sync(0xffffffffu, rm[mt][h], off));
    }
    float s0 = rm[0][0] + rm[0][1] + rm[1][0] + rm[1][1];   // token t0
    float s1 = rm[2][0] + rm[2][1] + rm[3][0] + rm[3][1];   // token t0+1
#pragma unroll
    for (int off = 4; off <= 16; off <<= 1) {
        s0 += __shfl_xor_sync(0xffffffffu, s0, off);
        s1 += __shfl_xor_sync(0xffffffffu, s1, off);
    }

    if (lane == 0) {
        out[(size_t)t0 * 256 + vout]       = scale * (0.7f * g0 + 0.3f * (s0 * (1.0f / 32.0f)));
        out[(size_t)(t0 + 1) * 256 + vout] = scale * (0.7f * g1 + 0.3f * (s1 * (1.0f / 32.0f)));
    }
}

// ---------------------------------------------------------------------------
extern "C" void kernel_launch(void* const* d_in, const int* in_sizes, int n_in,
                              void* d_out, int out_size) {
    const float* text    = (const float*)d_in[0];
    const float* clip    = (const float*)d_in[1];
    const float* concept = (const float*)d_in[2];
    const float* frame   = (const float*)d_in[3];
    const float* lsc     = (const float*)d_in[4];
    float* out = (float*)d_out;

    prep_kernel<<<GSIM_BLOCKS + NORM_BLOCKS, 256>>>(text, clip, concept, frame);

    cudaFuncSetAttribute(gemm_kernel, cudaFuncAttributeMaxDynamicSharedMemorySize,
                         SMEM_DYN);
    gemm_kernel<<<dim3(B_ROWS / 256, A_ROWS / 256), 512, SMEM_DYN>>>(lsc, out);
}

// round 17
// speedup vs baseline: 1.1261x; 1.1261x over previous
#include <cuda_runtime.h>
#include <cuda_fp16.h>
#include <cstdint>
#include <math.h>

// Shapes: text[256,512] f32, clip[256,512] f32, concept[256,32,512] f32,
// frame[256,64,512] f32, logit_scale scalar, out[256,256] f32.
// Big GEMM S[8192,16384] = nc @ nf^T in f16 (f16 acc), fused
// max-over-64-frames / mean-over-32-tokens epilogue; fp32 g_sim precomputed.
// compute_103 target: mma.sync + cp.async.bulk + mbarrier (no tcgen05).
// R17: best-measured gemm (R13: 2-stage bulk ring, single producer tid0,
// per-warp empty barrier, 2 CTAs/SM) + PDL overlap (griddepcontrol) so the
// gemm ramps up while the prep tail drains.

#define D_K     512
#define A_ROWS  8192
#define B_ROWS  16384
#define NCH     8             // 512 / 64 k-chunks (64 f16 = 128 B per row)
#define MT      64            // A images (128 rows) per chunk
#define NT      128           // B images (128 rows) per chunk
#define AIMG    16384         // 128 rows * 128 B
#define BIMG    16384
#define STAGE   49152         // 16 KB A + 32 KB B
#define SMEM_DYN (2 * STAGE + 64)   // + mbarrier slab
#define GSIM_BLOCKS 512       // 32 token-groups x 16 video-groups
#define NORM_BLOCKS 1536      // 24576 rows / 16 (half-warp per row)

// Packed, pre-swizzled f16 operand images:
//   g_ncp: [chunk(8)][mtile(64)][16384 B], g_nfp: [chunk(8)][ntile(128)][16384 B]
__device__ __align__(256) unsigned char g_ncp[(size_t)NCH * MT * AIMG];
__device__ __align__(256) unsigned char g_nfp[(size_t)NCH * NT * BIMG];
__device__ __align__(256) float g_gsim[256 * 256];

// ---------------------------------------------------------------------------
__device__ __forceinline__ uint32_t smem_u32(const void* p) {
    uint32_t a;
    asm("{ .reg .u64 t; cvta.to.shared.u64 t, %1; cvt.u32.u64 %0, t; }"
        : "=r"(a) : "l"(p));
    return a;
}
__device__ __forceinline__ void mbar_init(uint32_t a, uint32_t cnt) {
    asm volatile("mbarrier.init.shared.b64 [%0], %1;" :: "r"(a), "r"(cnt) : "memory");
}
__device__ __forceinline__ void mbar_expect_tx(uint32_t a, uint32_t bytes) {
    asm volatile("mbarrier.arrive.expect_tx.shared.b64 _, [%0], %1;"
                 :: "r"(a), "r"(bytes) : "memory");
}
__device__ __forceinline__ void mbar_arrive(uint32_t a) {
    asm volatile("mbarrier.arrive.release.cta.shared::cta.b64 _, [%0];"
                 :: "r"(a) : "memory");
}
#define MBAR_WAIT(mbar, parity) do {                                            \
    asm volatile("{\n\t.reg .pred P;\n"                                         \
        "LW_%=:\n\t"                                                            \
        "mbarrier.try_wait.parity.acquire.cta.shared::cta.b64 P, [%0], %1, 0x989680;\n\t" \
        "@P bra LD_%=;\n\t"                                                     \
        "bra LW_%=;\n"                                                          \
        "LD_%=:\n\t}"                                                           \
        :: "r"(mbar), "r"(parity) : "memory");                                  \
} while (0)
__device__ __forceinline__ void bulk_g2s(uint32_t dst, const void* src,
                                         uint32_t bytes, uint32_t mbar) {
    asm volatile(
        "cp.async.bulk.shared::cluster.global.mbarrier::complete_tx::bytes "
        "[%0], [%1], %2, [%3];"
        :: "r"(dst), "l"(src), "r"(bytes), "r"(mbar) : "memory");
}
__device__ __forceinline__ void fence_proxy_async_cta() {
    asm volatile("fence.proxy.async.shared::cta;" ::: "memory");
}
__device__ __forceinline__ void ldm_x4(uint32_t* r, uint32_t addr) {
    asm volatile("ldmatrix.sync.aligned.m8n8.x4.shared.b16 {%0,%1,%2,%3}, [%4];"
                 : "=r"(r[0]), "=r"(r[1]), "=r"(r[2]), "=r"(r[3]) : "r"(addr));
}
__device__ __forceinline__ void mma16816h(uint32_t* c, const uint32_t* a,
                                          uint32_t b0, uint32_t b1) {
    asm volatile(
        "mma.sync.aligned.m16n8k16.row.col.f16.f16.f16.f16 "
        "{%0,%1}, {%2,%3,%4,%5}, {%6,%7}, {%0,%1};"
        : "+r"(c[0]), "+r"(c[1])
        : "r"(a[0]), "r"(a[1]), "r"(a[2]), "r"(a[3]), "r"(b0), "r"(b1));
}
__device__ __forceinline__ void gdc_launch_dependents() {
    asm volatile("griddepcontrol.launch_dependents;" ::: "memory");
}
__device__ __forceinline__ void gdc_wait() {
    asm volatile("griddepcontrol.wait;" ::: "memory");
}

// ---------------------------------------------------------------------------
// Kernel 1 (single prep launch, 32 KB STATIC shared) — R14 layout:
//   blocks [0, 512): fp32 g_sim tile, 8 tokens x 16 videos, smem clip tile.
//   blocks [512, 2048): L2-normalize -> f16 swizzled images (half-warp/row).
// Each block triggers launch_dependents after its global stores.
// ---------------------------------------------------------------------------
__global__ __launch_bounds__(256) void prep_kernel(
    const float* __restrict__ text, const float* __restrict__ clip,
    const float* __restrict__ concept_e, const float* __restrict__ frame_e) {
    __shared__ float4 csh[16 * 128];            // 16 videos x 512 f32 = 32 KB
    int wid = threadIdx.x >> 5;
    int lane = threadIdx.x & 31;

    if (blockIdx.x < GSIM_BLOCKS) {
        int b = blockIdx.x;
        int tb = (b >> 4) * 8, vb = (b & 15) * 16;

        const float4* c4 = (const float4*)(clip + (size_t)vb * D_K);
#pragma unroll
        for (int i = 0; i < 8; i++)
            csh[threadIdx.x + i * 256] = c4[threadIdx.x + i * 256];
        __syncthreads();

        int t = tb + wid;
        float4 tv[4];
        const float4* tr = (const float4*)(text + (size_t)t * D_K);
#pragma unroll
        for (int j = 0; j < 4; j++) tv[j] = tr[lane * 4 + j];

        float acc[16];
#pragma unroll 1
        for (int v = 0; v < 16; v++) {
            const float4* cr = csh + v * 128;
            float g = 0.f;
#pragma unroll
            for (int j = 0; j < 4; j++) {
                float4 cv = cr[lane * 4 + j];
                g += tv[j].x * cv.x + tv[j].y * cv.y + tv[j].z * cv.z + tv[j].w * cv.w;
            }
            acc[v] = g;
        }
#pragma unroll
        for (int v = 0; v < 16; v++)
            acc[v] += __shfl_xor_sync(0xffffffffu, acc[v], 16);
#pragma unroll
        for (int off = 8; off > 0; off >>= 1) {
#pragma unroll
            for (int v = 0; v < off; v++) {
                float lo = acc[v], hi = acc[v + off];
                float sent = (lane & off) ? lo : hi;
                float recv = __shfl_xor_sync(0xffffffffu, sent, off);
                acc[v] = ((lane & off) ? hi : lo) + recv;
            }
        }
        if (lane < 16) g_gsim[(size_t)t * 256 + vb + lane] = acc[0];
        gdc_launch_dependents();
        return;
    }

    // ---- normalize + f16 + swizzled pack, half-warp per row ----
    int half = lane >> 4, hl = lane & 15;
    int R = (blockIdx.x - GSIM_BLOCKS) * 16 + wid * 2 + half;   // 0..24575

    const float* src;
    unsigned char* img;
    size_t chunk_stride;
    int rowin;
    if (R < A_ROWS) {
        src = concept_e + (size_t)R * D_K;
        img = g_ncp + (size_t)(R >> 7) * AIMG;
        rowin = R & 127;
        chunk_stride = (size_t)MT * AIMG;
    } else {
        int Rf = R - A_ROWS;
        src = frame_e + (size_t)Rf * D_K;
        img = g_nfp + (size_t)(Rf >> 7) * BIMG;
        rowin = Rf & 127;
        chunk_stride = (size_t)NT * BIMG;
    }

    int grp = hl >> 3, seg = hl & 7;
    float4 v[8];
    const float4* s4 = (const float4*)src;
#pragma unroll
    for (int p = 0; p < 4; p++) {
        int chunk = p * 2 + grp;
        int base4 = chunk * 16 + seg * 2;
        v[2 * p]     = s4[base4];
        v[2 * p + 1] = s4[base4 + 1];
    }

    float ss = 0.f;
#pragma unroll
    for (int i = 0; i < 8; i++)
        ss += v[i].x * v[i].x + v[i].y * v[i].y + v[i].z * v[i].z + v[i].w * v[i].w;
#pragma unroll
    for (int off = 8; off > 0; off >>= 1)
        ss += __shfl_xor_sync(0xffffffffu, ss, off);

    float inv = 1.0f / fmaxf(sqrtf(ss), 1e-12f);

    int soff = rowin * 128 + seg * 16;
    int swz = soff ^ ((soff >> 3) & 0x70);
#pragma unroll
    for (int p = 0; p < 4; p++) {
        union { __half2 h[4]; uint4 q; } u;
        u.h[0] = __float22half2_rn(make_float2(v[2*p].x * inv, v[2*p].y * inv));
        u.h[1] = __float22half2_rn(make_float2(v[2*p].z * inv, v[2*p].w * inv));
        u.h[2] = __float22half2_rn(make_float2(v[2*p+1].x * inv, v[2*p+1].y * inv));
        u.h[3] = __float22half2_rn(make_float2(v[2*p+1].z * inv, v[2*p+1].w * inv));
        int chunk = p * 2 + grp;
        *(uint4*)(img + (size_t)chunk * chunk_stride + swz) = u.q;
    }
    gdc_launch_dependents();
}

// ---------------------------------------------------------------------------
// Kernel 2 (R13 gemm + PDL): f16 HMMA GEMM, CTA 128x256 (K=512), warp 64x64,
// 2 CTAs/SM; 2-stage bulk ring, single producer (tid 0), per-warp empty
// barrier. Barrier init + address setup happen BEFORE griddepcontrol.wait.
// ---------------------------------------------------------------------------
__global__ void __launch_bounds__(256, 2) gemm_kernel(
    const float* __restrict__ lsc, float* __restrict__ out) {
    extern __shared__ unsigned char smem[];
    uint32_t sbase = smem_u32(smem);
    uint32_t full0 = sbase + 2 * STAGE;          // 8B each
    uint32_t full1 = full0 + 8;
    uint32_t emp0  = full0 + 16;
    uint32_t emp1  = full0 + 24;

    int tid = threadIdx.x, wid = tid >> 5, lane = tid & 31;
    int mtile = blockIdx.y, npair = blockIdx.x;
    int wm = wid >> 2, wn = wid & 3;             // 2M x 4N

    const unsigned char* asrc = g_ncp + (size_t)mtile * AIMG;
    const unsigned char* bsrc = g_nfp + (size_t)npair * (2 * BIMG);
    const size_t ACS = (size_t)MT * AIMG;
    const size_t BCS = (size_t)NT * BIMG;

    uint32_t Aoff[4], Axm[4];
#pragma unroll
    for (int mt = 0; mt < 4; mt++) {
        int row = wm * 64 + mt * 16 + (lane & 15);
        Aoff[mt] = row * 128;
        Axm[mt] = (row & 7) << 4;
    }
    uint32_t kA = (lane & 16);

    uint32_t Bimg = AIMG + (uint32_t)(wn >> 1) * BIMG;
    uint32_t Boff[4], Bxm[4];
#pragma unroll
    for (int bp = 0; bp < 4; bp++) {
        int row = (wn & 1) * 64 + bp * 16 + (lane & 7) + ((lane & 16) ? 8 : 0);
        Boff[bp] = row * 128;
        Bxm[bp] = (row & 7) << 4;
    }
    uint32_t kB = (lane & 8) ? 16u : 0u;

    uint32_t acc[4][8][2];
#pragma unroll
    for (int i = 0; i < 4; i++)
#pragma unroll
        for (int j = 0; j < 8; j++) { acc[i][j][0] = 0u; acc[i][j][1] = 0u; }

    if (tid == 0) {
        mbar_init(full0, 1);
        mbar_init(full1, 1);
        mbar_init(emp0, 8);      // one arrive per warp
        mbar_init(emp1, 8);
        fence_proxy_async_cta();
    }
    __syncthreads();

    // wait for prep output to be valid, then start the pipeline + preload
    gdc_wait();

    int t0 = mtile * 4 + wm * 2;
    int vout = npair * 4 + wn;
    float scale = fminf(expf(lsc[0]), 100.0f);
    float g0 = __ldg(&g_gsim[(size_t)t0 * 256 + vout]);
    float g1 = __ldg(&g_gsim[(size_t)(t0 + 1) * 256 + vout]);

    if (tid == 0) {
        mbar_expect_tx(full0, STAGE);
        bulk_g2s(sbase,        asrc, AIMG,     full0);
        bulk_g2s(sbase + AIMG, bsrc, 2 * BIMG, full0);
    }

#pragma unroll 1
    for (int c = 0; c < NCH; c++) {
        // single producer: tid 0 prefetches chunk c+1 (R13 best-measured)
        if (tid == 0 && c + 1 < NCH) {
            int cn = c + 1;
            uint32_t dst = sbase + (cn & 1) * STAGE;
            uint32_t fb = (cn & 1) ? full1 : full0;
            uint32_t eb = (cn & 1) ? emp1 : emp0;
            if (cn >= 2) MBAR_WAIT(eb, ((cn >> 1) - 1) & 1);
            mbar_expect_tx(fb, STAGE);
            bulk_g2s(dst,        asrc + cn * ACS, AIMG,     fb);
            bulk_g2s(dst + AIMG, bsrc + cn * BCS, 2 * BIMG, fb);
        }

        MBAR_WAIT((c & 1) ? full1 : full0, (c >> 1) & 1);

        uint32_t sa = sbase + (c & 1) * STAGE;
        uint32_t sb = sa + Bimg;

#pragma unroll
        for (int ks = 0; ks < 4; ks++) {
            uint32_t kb = ks * 32;
            uint32_t a[4][4];
#pragma unroll
            for (int mt = 0; mt < 4; mt++)
                ldm_x4(a[mt], sa + Aoff[mt] + ((kb + kA) ^ Axm[mt]));
#pragma unroll
            for (int bp = 0; bp < 4; bp++) {
                uint32_t b[4];
                ldm_x4(b, sb + Boff[bp] + ((kb + kB) ^ Bxm[bp]));
#pragma unroll
                for (int mt = 0; mt < 4; mt++) {
                    mma16816h(acc[mt][2 * bp],     a[mt], b[0], b[1]);
                    mma16816h(acc[mt][2 * bp + 1], a[mt], b[2], b[3]);
                }
            }
        }
        // this warp is done reading stage (c&1); release-arrive on empty
        if (lane == 0) mbar_arrive((c & 1) ? emp1 : emp0);
    }

    // ---- fused epilogue (register-only) ----
    float rm[4][2];
#pragma unroll
    for (int mt = 0; mt < 4; mt++)
#pragma unroll
        for (int h = 0; h < 2; h++) {
            __half2 m = __halves2half2(__ushort_as_half(0xFBFFu),
                                       __ushort_as_half(0xFBFFu));  // -65504
#pragma unroll
            for (int np = 0; np < 8; np++)
                m = __hmax2(m, *(__half2*)&acc[mt][np][h]);
            float2 f = __half22float2(m);
            rm[mt][h] = fmaxf(f.x, f.y);
        }
#pragma unroll
    for (int off = 1; off <= 2; off <<= 1) {
#pragma unroll
        for (int mt = 0; mt < 4; mt++)
#pragma unroll
            for (int h = 0; h < 2; h++)
                rm[mt][h] = fmaxf(rm[mt][h],
                                  __shfl_xor_sync(0xffffffffu, rm[mt][h], off));
    }
    float s0 = rm[0][0] + rm[0][1] + rm[1][0] + rm[1][1];
    float s1 = rm[2][0] + rm[2][1] + rm[3][0] + rm[3][1];
#pragma unroll
    for (int off = 4; off <= 16; off <<= 1) {
        s0 += __shfl_xor_sync(0xffffffffu, s0, off);
        s1 += __shfl_xor_sync(0xffffffffu, s1, off);
    }

    if (lane == 0) {
        out[(size_t)t0 * 256 + vout]       = scale * (0.7f * g0 + 0.3f * (s0 * (1.0f / 32.0f)));
        out[(size_t)(t0 + 1) * 256 + vout] = scale * (0.7f * g1 + 0.3f * (s1 * (1.0f / 32.0f)));
    }
}

// ---------------------------------------------------------------------------
extern "C" void kernel_launch(void* const* d_in, const int* in_sizes, int n_in,
                              void* d_out, int out_size) {
    const float* text    = (const float*)d_in[0];
    const float* clip    = (const float*)d_in[1];
    const float* concept = (const float*)d_in[2];
    const float* frame   = (const float*)d_in[3];
    const float* lsc     = (const float*)d_in[4];
    float* out = (float*)d_out;

    prep_kernel<<<GSIM_BLOCKS + NORM_BLOCKS, 256>>>(text, clip, concept, frame);

    cudaFuncSetAttribute(gemm_kernel, cudaFuncAttributeMaxDynamicSharedMemorySize,
                         SMEM_DYN);

    // gemm with programmatic dependent launch: ramps up under prep's tail,
    // griddepcontrol.wait gates the first read of prep output.
    cudaLaunchConfig_t cfg = {};
    cfg.gridDim = dim3(NT / 2, MT);
    cfg.blockDim = dim3(256);
    cfg.dynamicSmemBytes = SMEM_DYN;
    cudaLaunchAttribute attrs[1];
    attrs[0].id = cudaLaunchAttributeProgrammaticStreamSerialization;
    attrs[0].val.programmaticStreamSerializationAllowed = 1;
    cfg.attrs = attrs;
    cfg.numAttrs = 1;
    cudaLaunchKernelEx(&cfg, gemm_kernel, lsc, out);
}